// round 7
// baseline (speedup 1.0000x reference)
#include <cuda_runtime.h>
#include <cuda_fp16.h>
#include <cstdint>

// ============================================================================
// Scratch (static __device__ arrays — allocation-free per harness rules)
// ============================================================================
__device__ __half g_hx_h[8192 * 1024];          // hx rounded to fp16 (16 MB)
__device__ __half g_w_h[4096 * 1024];           // W_hh rounded to fp16 (8 MB)
__device__ __half g_hgraw[8192UL * 4096UL];     // hx@W^T in fp16 (64 MB)

#define DEVINL __device__ __forceinline__

DEVINL uint32_t smem_to_u32(const void* p) {
    uint32_t a;
    asm("{ .reg .u64 t; cvta.to.shared.u64 t, %1; cvt.u32.u64 %0, t; }"
        : "=r"(a) : "l"(p));
    return a;
}

DEVINL void cp_async16(uint32_t dst_smem, const void* src_gmem) {
    asm volatile("cp.async.cg.shared.global [%0], [%1], 16;"
                 :: "r"(dst_smem), "l"(src_gmem));
}
#define CP_ASYNC_COMMIT() asm volatile("cp.async.commit_group;" ::: "memory")
#define CP_ASYNC_WAIT_GROUP(n) \
    asm volatile("cp.async.wait_group %0;" :: "n"(n) : "memory")

DEVINL void ldsm_x4(uint32_t* r, uint32_t addr) {
    asm volatile("ldmatrix.sync.aligned.m8n8.x4.shared.b16 {%0,%1,%2,%3}, [%4];"
                 : "=r"(r[0]), "=r"(r[1]), "=r"(r[2]), "=r"(r[3])
                 : "r"(addr));
}

// D += A * B  (m16n8k16, fp16 in, f32 acc)
#define MMA_F16(d, a, b0, b1)                                                \
    asm volatile(                                                            \
        "mma.sync.aligned.m16n8k16.row.col.f32.f16.f16.f32 "                 \
        "{%0,%1,%2,%3}, {%4,%5,%6,%7}, {%8,%9}, {%0,%1,%2,%3};"              \
        : "+f"((d)[0]), "+f"((d)[1]), "+f"((d)[2]), "+f"((d)[3])             \
        : "r"((a)[0]), "r"((a)[1]), "r"((a)[2]), "r"((a)[3]),                \
          "r"(b0), "r"(b1))

DEVINL float4 ldcs4(const float* p) {
    float4 v;
    asm volatile("ld.global.cs.v4.f32 {%0,%1,%2,%3}, [%4];"
                 : "=f"(v.x), "=f"(v.y), "=f"(v.z), "=f"(v.w) : "l"(p));
    return v;
}
DEVINL uint2 ldcs_u2(const void* p) {
    uint2 v;
    asm volatile("ld.global.cs.v2.b32 {%0,%1}, [%2];"
                 : "=r"(v.x), "=r"(v.y) : "l"(p));
    return v;
}
DEVINL void stcs_u32(void* p, uint32_t v) {
    asm volatile("st.global.cs.b32 [%0], %1;" :: "l"(p), "r"(v));
}
DEVINL void stcs4(float* p, float4 v) {
    asm volatile("st.global.cs.v4.f32 [%0], {%1,%2,%3,%4};"
                 :: "l"(p), "f"(v.x), "f"(v.y), "f"(v.z), "f"(v.w));
}

// ============================================================================
// Constants
// ============================================================================
static constexpr int B_DIM = 8192;
static constexpr int H_DIM = 1024;
static constexpr int FH_DIM = 4096;

static constexpr int TM = 128;
static constexpr int TN = 128;
static constexpr int TK = 64;             // fp16 elems per stage row (128 B)
static constexpr int STAGES = 3;
static constexpr int NK = H_DIM / TK;     // 16

static constexpr int A_BYTES = TM * TK * 2;          // 16384
static constexpr int B_BYTES = TN * TK * 2;          // 16384
static constexpr int STG_BYTES = A_BYTES + B_BYTES;  // 32768
static constexpr int SMEM_BYTES = STAGES * STG_BYTES; // 98304 (2 CTAs/SM)

// ============================================================================
// Kernel 0: round fp32 -> fp16 (RN). 1M threads, 3 independent float4 each
// (2 from hx, 1 from W) hoisted up front for max MLP. No loop, no branch.
// ============================================================================
static constexpr int HX_N4 = (B_DIM * H_DIM) / 4;       // 2M
static constexpr int W_N4  = (FH_DIM * H_DIM) / 4;      // 1M

DEVINL uint2 f4_to_h4(float4 v) {
    __half2 lo = __floats2half2_rn(v.x, v.y);
    __half2 hi = __floats2half2_rn(v.z, v.w);
    return make_uint2(*(uint32_t*)&lo, *(uint32_t*)&hi);
}

__global__ __launch_bounds__(256) void round_all_kernel(
    const float* __restrict__ hx, const float* __restrict__ w) {
    const int i = blockIdx.x * blockDim.x + threadIdx.x;   // 0 .. 1M-1
    // three independent loads, issued back-to-back (MLP=3)
    float4 a = ((const float4*)hx)[i];
    float4 b = ((const float4*)hx)[i + W_N4];              // hx upper half
    float4 c = ((const float4*)w)[i];
    ((uint2*)g_hx_h)[i]          = f4_to_h4(a);
    ((uint2*)g_hx_h)[i + W_N4]   = f4_to_h4(b);
    ((uint2*)g_w_h)[i]           = f4_to_h4(c);
}

// ============================================================================
// Kernel 1: fp16 mma.sync GEMM   g_hgraw[m][n] = sum_k hx[m][k] * W[n][k]
//  CTA 128x128, 4 warps (2m x 2n), warp tile 64x64, m16n8k16.
//  3-stage cp.async pipeline, 2 CTAs/SM, double-buffered ldmatrix fragments.
//  (At the legacy-HMMA issue floor; further GEMM tuning is unproductive.)
// ============================================================================
__global__ __launch_bounds__(128, 2) void gemm_f16_kernel() {
    extern __shared__ char smem[];
    const uint32_t sb = smem_to_u32(smem);
    const int tid = threadIdx.x;
    const int lane = tid & 31;
    const int wid = tid >> 5;
    const int wm = wid & 1;       // 0..1 (m)
    const int wn = wid >> 1;      // 0..1 (n)

    const int m_base = blockIdx.y * TM;
    const int n_base = blockIdx.x * TN;
    const __half* Ag = g_hx_h + (size_t)m_base * H_DIM;
    const __half* Bg = g_w_h + (size_t)n_base * H_DIM;

    float acc[4][8][4];
#pragma unroll
    for (int i = 0; i < 4; i++)
#pragma unroll
        for (int j = 0; j < 8; j++)
#pragma unroll
            for (int e = 0; e < 4; e++) acc[i][j][e] = 0.f;

    auto load_stage = [&](int kt) {
        const uint32_t ab = sb + (uint32_t)(kt % STAGES) * STG_BYTES;
        const uint32_t bb = ab + A_BYTES;
#pragma unroll
        for (int i = 0; i < 8; i++) {           // A: 128 rows x 8 chunks
            int slot = tid + i * 128;
            int row = slot >> 3, c = slot & 7;
            uint32_t dst = ab + (uint32_t)row * 128u + (uint32_t)((c ^ (row & 7)) * 16);
            cp_async16(dst, Ag + (size_t)row * H_DIM + kt * TK + c * 8);
        }
#pragma unroll
        for (int i = 0; i < 8; i++) {           // B: 128 rows x 8 chunks
            int slot = tid + i * 128;
            int row = slot >> 3, c = slot & 7;
            uint32_t dst = bb + (uint32_t)row * 128u + (uint32_t)((c ^ (row & 7)) * 16);
            cp_async16(dst, Bg + (size_t)row * H_DIM + kt * TK + c * 8);
        }
    };

#pragma unroll
    for (int s = 0; s < STAGES - 1; s++) {
        load_stage(s);
        CP_ASYNC_COMMIT();
    }

    const int r16 = lane & 15;
    const int chi = lane >> 4;

    uint32_t afrag[2][4][4], bfrag[2][4][4];

    auto load_frags = [&](int buf, uint32_t ab, uint32_t bb, int ks) {
        const int ch = 2 * ks + chi;
#pragma unroll
        for (int mt = 0; mt < 4; mt++) {
            int row = wm * 64 + mt * 16 + r16;
            ldsm_x4(afrag[buf][mt], ab + (uint32_t)row * 128u +
                                        (uint32_t)((ch ^ (row & 7)) * 16));
        }
#pragma unroll
        for (int p = 0; p < 4; p++) {
            int row = wn * 64 + p * 16 + r16;
            ldsm_x4(bfrag[buf][p], bb + (uint32_t)row * 128u +
                                       (uint32_t)((ch ^ (row & 7)) * 16));
        }
    };

    auto do_mmas = [&](int buf) {
#pragma unroll
        for (int mt = 0; mt < 4; mt++) {
#pragma unroll
            for (int p = 0; p < 4; p++) {
                MMA_F16(acc[mt][2 * p + 0], afrag[buf][mt],
                        bfrag[buf][p][0], bfrag[buf][p][2]);
                MMA_F16(acc[mt][2 * p + 1], afrag[buf][mt],
                        bfrag[buf][p][1], bfrag[buf][p][3]);
            }
        }
    };

    for (int kt = 0; kt < NK; kt++) {
        CP_ASYNC_WAIT_GROUP(1);
        __syncthreads();

        if (kt + STAGES - 1 < NK) load_stage(kt + STAGES - 1);
        CP_ASYNC_COMMIT();

        const uint32_t ab = sb + (uint32_t)(kt % STAGES) * STG_BYTES;
        const uint32_t bb = ab + A_BYTES;

        load_frags(0, ab, bb, 0);
#pragma unroll
        for (int ks = 0; ks < 4; ks++) {
            if (ks < 3) load_frags((ks + 1) & 1, ab, bb, ks + 1);
            do_mmas(ks & 1);
        }
    }

#pragma unroll
    for (int mt = 0; mt < 4; mt++) {
#pragma unroll
        for (int nt = 0; nt < 8; nt++) {
            const int row = m_base + wm * 64 + mt * 16 + (lane >> 2);
            const int col = n_base + wn * 64 + nt * 8 + (lane & 3) * 2;
            __half2 lo = __floats2half2_rn(acc[mt][nt][0], acc[mt][nt][1]);
            __half2 hi = __floats2half2_rn(acc[mt][nt][2], acc[mt][nt][3]);
            stcs_u32(g_hgraw + (size_t)row * FH_DIM + col, *(uint32_t*)&lo);
            stcs_u32(g_hgraw + (size_t)(row + 8) * FH_DIM + col, *(uint32_t*)&hi);
        }
    }
}

// ============================================================================
// Kernel 2: fused LN(hgates) + gates + LN(c) + outputs. One CTA per row.
//  tanh via exact identity 2*sigm(2x)-1 (single __expf) — no libm tanhf.
// ============================================================================
DEVINL float sigm(float x) { return 1.0f / (1.0f + __expf(-x)); }
DEVINL float ftanh(float x) { return 2.0f * sigm(2.0f * x) - 1.0f; }

__global__ __launch_bounds__(256, 6) void lstm_ln_kernel(
    const float* __restrict__ inp,
    const float* __restrict__ cx,
    const float* __restrict__ gh, const float* __restrict__ bh,
    const float* __restrict__ gc, const float* __restrict__ bc,
    float* __restrict__ out)
{
    __shared__ float red1[16];
    __shared__ float red2[16];
    const int b = blockIdx.x;
    const int t = threadIdx.x;
    const int w = t >> 5, l = t & 31;

    const __half* hgp = g_hgraw + (size_t)b * FH_DIM;
    const float* ipp = inp + (size_t)b * FH_DIM;

    // Hoist per-row hgates loads up front — streaming, read-once.
    float v[4][4];
#pragma unroll
    for (int q = 0; q < 4; q++) {
        uint2 u = ldcs_u2(hgp + q * 1024 + t * 4);
        float2 lo = __half22float2(*(__half2*)&u.x);
        float2 hi = __half22float2(*(__half2*)&u.y);
        v[q][0] = lo.x; v[q][1] = lo.y; v[q][2] = hi.x; v[q][3] = hi.y;
    }
    float4 cxv = ldcs4(cx + (size_t)b * H_DIM + t * 4);

    float s = 0.f, ss = 0.f;
#pragma unroll
    for (int q = 0; q < 4; q++)
#pragma unroll
        for (int e = 0; e < 4; e++) { s += v[q][e]; ss += v[q][e] * v[q][e]; }
#pragma unroll
    for (int o = 16; o > 0; o >>= 1) {
        s  += __shfl_xor_sync(0xffffffffu, s, o);
        ss += __shfl_xor_sync(0xffffffffu, ss, o);
    }
    if (l == 0) { red1[w] = s; red1[8 + w] = ss; }
    __syncthreads();
    float ts = 0.f, tss = 0.f;
#pragma unroll
    for (int q = 0; q < 8; q++) { ts += red1[q]; tss += red1[8 + q]; }
    const float mu1 = ts * (1.0f / 4096.0f);
    const float var1 = tss * (1.0f / 4096.0f) - mu1 * mu1;
    const float rs1 = rsqrtf(var1 + 1e-5f);

    // gates = input + LN(hgates)*gamma_h + beta_h
    float gate[4][4];
#pragma unroll
    for (int q = 0; q < 4; q++) {
        float4 gv = __ldg((const float4*)gh + q * 256 + t);
        float4 bv = __ldg((const float4*)bh + q * 256 + t);
        float4 ivq = ldcs4(ipp + q * 1024 + t * 4);
        const float* gp = (const float*)&gv;
        const float* bp = (const float*)&bv;
        const float* pp = (const float*)&ivq;
#pragma unroll
        for (int e = 0; e < 4; e++)
            gate[q][e] = pp[e] + (v[q][e] - mu1) * rs1 * gp[e] + bp[e];
    }

    const float* cxp = (const float*)&cxv;

    float og[4], cc[4];
    float s2 = 0.f, ss2 = 0.f;
#pragma unroll
    for (int e = 0; e < 4; e++) {
        const float ig = sigm(gate[0][e]);
        const float fg = sigm(gate[1][e]);
        const float cg = ftanh(gate[2][e]);
        og[e] = sigm(gate[3][e]);
        cc[e] = fg * cxp[e] + ig * cg;
        s2 += cc[e];
        ss2 += cc[e] * cc[e];
    }
#pragma unroll
    for (int o = 16; o > 0; o >>= 1) {
        s2  += __shfl_xor_sync(0xffffffffu, s2, o);
        ss2 += __shfl_xor_sync(0xffffffffu, ss2, o);
    }
    if (l == 0) { red2[w] = s2; red2[8 + w] = ss2; }
    __syncthreads();
    float ts2 = 0.f, tss2 = 0.f;
#pragma unroll
    for (int q = 0; q < 8; q++) { ts2 += red2[q]; tss2 += red2[8 + q]; }
    const float mu2 = ts2 * (1.0f / 1024.0f);
    const float var2 = tss2 * (1.0f / 1024.0f) - mu2 * mu2;
    const float rs2 = rsqrtf(var2 + 1e-5f);

    float4 gcv = __ldg((const float4*)gc + t);
    float4 bcv = __ldg((const float4*)bc + t);
    const float* gcp = (const float*)&gcv;
    const float* bcp = (const float*)&bcv;

    float4 hy4, cy4;
    float* hyp = (float*)&hy4;
    float* cyp = (float*)&cy4;
#pragma unroll
    for (int e = 0; e < 4; e++) {
        const float cyv = (cc[e] - mu2) * rs2 * gcp[e] + bcp[e];
        cyp[e] = cyv;
        hyp[e] = og[e] * ftanh(cyv);
    }

    stcs4(out + (size_t)b * H_DIM + t * 4, hy4);
    stcs4(out + (size_t)B_DIM * H_DIM + (size_t)b * H_DIM + t * 4, cy4);
}

// ============================================================================
// Entry point
// ============================================================================
extern "C" void kernel_launch(void* const* d_in, const int* in_sizes, int n_in,
                              void* d_out, int out_size) {
    (void)in_sizes; (void)n_in; (void)out_size;
    const float* inp = (const float*)d_in[0];
    const float* hx  = (const float*)d_in[1];
    const float* cx  = (const float*)d_in[2];
    const float* w   = (const float*)d_in[3];
    const float* gh  = (const float*)d_in[4];
    const float* bh  = (const float*)d_in[5];
    const float* gc  = (const float*)d_in[6];
    const float* bc  = (const float*)d_in[7];
    float* out = (float*)d_out;

    round_all_kernel<<<W_N4 / 256, 256>>>(hx, w);

    cudaFuncSetAttribute(gemm_f16_kernel,
                         cudaFuncAttributeMaxDynamicSharedMemorySize,
                         SMEM_BYTES);
    gemm_f16_kernel<<<dim3(FH_DIM / TN, B_DIM / TM), 128, SMEM_BYTES>>>();

    lstm_ln_kernel<<<B_DIM, 256>>>(inp, cx, gh, bh, gc, bc, out);
}

// round 8
// speedup vs baseline: 1.0076x; 1.0076x over previous
#include <cuda_runtime.h>
#include <cuda_fp16.h>
#include <cstdint>

// ============================================================================
// Scratch (static __device__ arrays — allocation-free per harness rules)
// ============================================================================
__device__ __half g_hx_h[8192 * 1024];          // hx rounded to fp16 (16 MB)
__device__ __half g_w_h[4096 * 1024];           // W_hh rounded to fp16 (8 MB)
__device__ __half g_hgraw[8192UL * 4096UL];     // hx@W^T fp16 (64 MB, L2-resident)

#define DEVINL __device__ __forceinline__

DEVINL uint32_t smem_to_u32(const void* p) {
    uint32_t a;
    asm("{ .reg .u64 t; cvta.to.shared.u64 t, %1; cvt.u32.u64 %0, t; }"
        : "=r"(a) : "l"(p));
    return a;
}

DEVINL void cp_async16(uint32_t dst_smem, const void* src_gmem) {
    asm volatile("cp.async.cg.shared.global [%0], [%1], 16;"
                 :: "r"(dst_smem), "l"(src_gmem));
}
#define CP_ASYNC_COMMIT() asm volatile("cp.async.commit_group;" ::: "memory")
#define CP_ASYNC_WAIT_GROUP(n) \
    asm volatile("cp.async.wait_group %0;" :: "n"(n) : "memory")

DEVINL void ldsm_x4(uint32_t* r, uint32_t addr) {
    asm volatile("ldmatrix.sync.aligned.m8n8.x4.shared.b16 {%0,%1,%2,%3}, [%4];"
                 : "=r"(r[0]), "=r"(r[1]), "=r"(r[2]), "=r"(r[3])
                 : "r"(addr));
}

// D += A * B  (m16n8k16, fp16 in, f32 acc)
#define MMA_F16(d, a, b0, b1)                                                \
    asm volatile(                                                            \
        "mma.sync.aligned.m16n8k16.row.col.f32.f16.f16.f32 "                 \
        "{%0,%1,%2,%3}, {%4,%5,%6,%7}, {%8,%9}, {%0,%1,%2,%3};"              \
        : "+f"((d)[0]), "+f"((d)[1]), "+f"((d)[2]), "+f"((d)[3])             \
        : "r"((a)[0]), "r"((a)[1]), "r"((a)[2]), "r"((a)[3]),                \
          "r"(b0), "r"(b1))

DEVINL float4 ldcs4(const float* p) {
    float4 v;
    asm volatile("ld.global.cs.v4.f32 {%0,%1,%2,%3}, [%4];"
                 : "=f"(v.x), "=f"(v.y), "=f"(v.z), "=f"(v.w) : "l"(p));
    return v;
}
DEVINL void stcs4(float* p, float4 v) {
    asm volatile("st.global.cs.v4.f32 [%0], {%1,%2,%3,%4};"
                 :: "l"(p), "f"(v.x), "f"(v.y), "f"(v.z), "f"(v.w));
}

// ============================================================================
// Constants
// ============================================================================
static constexpr int B_DIM = 8192;
static constexpr int H_DIM = 1024;
static constexpr int FH_DIM = 4096;

static constexpr int TM = 128;
static constexpr int TN = 128;
static constexpr int TK = 64;             // fp16 elems per stage row (128 B)
static constexpr int STAGES = 3;
static constexpr int NK = H_DIM / TK;     // 16

static constexpr int A_BYTES = TM * TK * 2;          // 16384
static constexpr int B_BYTES = TN * TK * 2;          // 16384
static constexpr int STG_BYTES = A_BYTES + B_BYTES;  // 32768
static constexpr int SMEM_BYTES = STAGES * STG_BYTES; // 98304 (2 CTAs/SM)

// ============================================================================
// Kernel 0: round fp32 -> fp16 (RN). 1M threads, 3 independent float4 each.
// ============================================================================
static constexpr int HX_N4 = (B_DIM * H_DIM) / 4;       // 2M
static constexpr int W_N4  = (FH_DIM * H_DIM) / 4;      // 1M

DEVINL uint2 f4_to_h4(float4 v) {
    __half2 lo = __floats2half2_rn(v.x, v.y);
    __half2 hi = __floats2half2_rn(v.z, v.w);
    return make_uint2(*(uint32_t*)&lo, *(uint32_t*)&hi);
}

__global__ __launch_bounds__(256) void round_all_kernel(
    const float* __restrict__ hx, const float* __restrict__ w) {
    const int i = blockIdx.x * blockDim.x + threadIdx.x;   // 0 .. 1M-1
    float4 a = ((const float4*)hx)[i];
    float4 b = ((const float4*)hx)[i + W_N4];
    float4 c = ((const float4*)w)[i];
    ((uint2*)g_hx_h)[i]          = f4_to_h4(a);
    ((uint2*)g_hx_h)[i + W_N4]   = f4_to_h4(b);
    ((uint2*)g_w_h)[i]           = f4_to_h4(c);
}

// ============================================================================
// Kernel 1: fp16 mma.sync GEMM   g_hgraw[m][n] = sum_k hx[m][k] * W[n][k]
//  CTA 128x128, 4 warps (2m x 2n), warp tile 64x64, m16n8k16.
//  3-stage cp.async pipeline, 2 CTAs/SM, double-buffered ldmatrix fragments.
//  hgraw stored with DEFAULT policy -> stays resident in the 126MB L2 for
//  the epilogue (the .cs streams elsewhere won't evict it).
// ============================================================================
__global__ __launch_bounds__(128, 2) void gemm_f16_kernel() {
    extern __shared__ char smem[];
    const uint32_t sb = smem_to_u32(smem);
    const int tid = threadIdx.x;
    const int lane = tid & 31;
    const int wid = tid >> 5;
    const int wm = wid & 1;       // 0..1 (m)
    const int wn = wid >> 1;      // 0..1 (n)

    const int m_base = blockIdx.y * TM;
    const int n_base = blockIdx.x * TN;
    const __half* Ag = g_hx_h + (size_t)m_base * H_DIM;
    const __half* Bg = g_w_h + (size_t)n_base * H_DIM;

    float acc[4][8][4];
#pragma unroll
    for (int i = 0; i < 4; i++)
#pragma unroll
        for (int j = 0; j < 8; j++)
#pragma unroll
            for (int e = 0; e < 4; e++) acc[i][j][e] = 0.f;

    auto load_stage = [&](int kt) {
        const uint32_t ab = sb + (uint32_t)(kt % STAGES) * STG_BYTES;
        const uint32_t bb = ab + A_BYTES;
#pragma unroll
        for (int i = 0; i < 8; i++) {           // A: 128 rows x 8 chunks
            int slot = tid + i * 128;
            int row = slot >> 3, c = slot & 7;
            uint32_t dst = ab + (uint32_t)row * 128u + (uint32_t)((c ^ (row & 7)) * 16);
            cp_async16(dst, Ag + (size_t)row * H_DIM + kt * TK + c * 8);
        }
#pragma unroll
        for (int i = 0; i < 8; i++) {           // B: 128 rows x 8 chunks
            int slot = tid + i * 128;
            int row = slot >> 3, c = slot & 7;
            uint32_t dst = bb + (uint32_t)row * 128u + (uint32_t)((c ^ (row & 7)) * 16);
            cp_async16(dst, Bg + (size_t)row * H_DIM + kt * TK + c * 8);
        }
    };

#pragma unroll
    for (int s = 0; s < STAGES - 1; s++) {
        load_stage(s);
        CP_ASYNC_COMMIT();
    }

    const int r16 = lane & 15;
    const int chi = lane >> 4;

    uint32_t afrag[2][4][4], bfrag[2][4][4];

    auto load_frags = [&](int buf, uint32_t ab, uint32_t bb, int ks) {
        const int ch = 2 * ks + chi;
#pragma unroll
        for (int mt = 0; mt < 4; mt++) {
            int row = wm * 64 + mt * 16 + r16;
            ldsm_x4(afrag[buf][mt], ab + (uint32_t)row * 128u +
                                        (uint32_t)((ch ^ (row & 7)) * 16));
        }
#pragma unroll
        for (int p = 0; p < 4; p++) {
            int row = wn * 64 + p * 16 + r16;
            ldsm_x4(bfrag[buf][p], bb + (uint32_t)row * 128u +
                                       (uint32_t)((ch ^ (row & 7)) * 16));
        }
    };

    auto do_mmas = [&](int buf) {
#pragma unroll
        for (int mt = 0; mt < 4; mt++) {
#pragma unroll
            for (int p = 0; p < 4; p++) {
                MMA_F16(acc[mt][2 * p + 0], afrag[buf][mt],
                        bfrag[buf][p][0], bfrag[buf][p][2]);
                MMA_F16(acc[mt][2 * p + 1], afrag[buf][mt],
                        bfrag[buf][p][1], bfrag[buf][p][3]);
            }
        }
    };

    for (int kt = 0; kt < NK; kt++) {
        CP_ASYNC_WAIT_GROUP(1);
        __syncthreads();

        if (kt + STAGES - 1 < NK) load_stage(kt + STAGES - 1);
        CP_ASYNC_COMMIT();

        const uint32_t ab = sb + (uint32_t)(kt % STAGES) * STG_BYTES;
        const uint32_t bb = ab + A_BYTES;

        load_frags(0, ab, bb, 0);
#pragma unroll
        for (int ks = 0; ks < 4; ks++) {
            if (ks < 3) load_frags((ks + 1) & 1, ab, bb, ks + 1);
            do_mmas(ks & 1);
        }
    }

    // ---- epilogue: accumulators -> g_hgraw as fp16 (DEFAULT policy: L2-resident)
#pragma unroll
    for (int mt = 0; mt < 4; mt++) {
#pragma unroll
        for (int nt = 0; nt < 8; nt++) {
            const int row = m_base + wm * 64 + mt * 16 + (lane >> 2);
            const int col = n_base + wn * 64 + nt * 8 + (lane & 3) * 2;
            __half2 lo = __floats2half2_rn(acc[mt][nt][0], acc[mt][nt][1]);
            __half2 hi = __floats2half2_rn(acc[mt][nt][2], acc[mt][nt][3]);
            *(uint32_t*)(g_hgraw + (size_t)row * FH_DIM + col) = *(uint32_t*)&lo;
            *(uint32_t*)(g_hgraw + (size_t)(row + 8) * FH_DIM + col) = *(uint32_t*)&hi;
        }
    }
}

// ============================================================================
// Kernel 2: fused LN(hgates) + gates + LN(c) + outputs. One CTA per row.
//  hgraw read with default policy (L2 hits); true streams use .cs.
// ============================================================================
DEVINL float sigm(float x) { return 1.0f / (1.0f + __expf(-x)); }
DEVINL float ftanh(float x) { return 2.0f * sigm(2.0f * x) - 1.0f; }

__global__ __launch_bounds__(256, 6) void lstm_ln_kernel(
    const float* __restrict__ inp,
    const float* __restrict__ cx,
    const float* __restrict__ gh, const float* __restrict__ bh,
    const float* __restrict__ gc, const float* __restrict__ bc,
    float* __restrict__ out)
{
    __shared__ float red1[16];
    __shared__ float red2[16];
    const int b = blockIdx.x;
    const int t = threadIdx.x;
    const int w = t >> 5, l = t & 31;

    const __half* hgp = g_hgraw + (size_t)b * FH_DIM;
    const float* ipp = inp + (size_t)b * FH_DIM;

    // Hoist per-row hgates loads up front (L2-resident -> low latency).
    float v[4][4];
#pragma unroll
    for (int q = 0; q < 4; q++) {
        uint2 u = *(const uint2*)(hgp + q * 1024 + t * 4);
        float2 lo = __half22float2(*(__half2*)&u.x);
        float2 hi = __half22float2(*(__half2*)&u.y);
        v[q][0] = lo.x; v[q][1] = lo.y; v[q][2] = hi.x; v[q][3] = hi.y;
    }
    float4 cxv = ldcs4(cx + (size_t)b * H_DIM + t * 4);

    float s = 0.f, ss = 0.f;
#pragma unroll
    for (int q = 0; q < 4; q++)
#pragma unroll
        for (int e = 0; e < 4; e++) { s += v[q][e]; ss += v[q][e] * v[q][e]; }
#pragma unroll
    for (int o = 16; o > 0; o >>= 1) {
        s  += __shfl_xor_sync(0xffffffffu, s, o);
        ss += __shfl_xor_sync(0xffffffffu, ss, o);
    }
    if (l == 0) { red1[w] = s; red1[8 + w] = ss; }
    __syncthreads();
    float ts = 0.f, tss = 0.f;
#pragma unroll
    for (int q = 0; q < 8; q++) { ts += red1[q]; tss += red1[8 + q]; }
    const float mu1 = ts * (1.0f / 4096.0f);
    const float var1 = tss * (1.0f / 4096.0f) - mu1 * mu1;
    const float rs1 = rsqrtf(var1 + 1e-5f);

    // gates = input + LN(hgates)*gamma_h + beta_h
    float gate[4][4];
#pragma unroll
    for (int q = 0; q < 4; q++) {
        float4 gv = __ldg((const float4*)gh + q * 256 + t);
        float4 bv = __ldg((const float4*)bh + q * 256 + t);
        float4 ivq = ldcs4(ipp + q * 1024 + t * 4);
        const float* gp = (const float*)&gv;
        const float* bp = (const float*)&bv;
        const float* pp = (const float*)&ivq;
#pragma unroll
        for (int e = 0; e < 4; e++)
            gate[q][e] = pp[e] + (v[q][e] - mu1) * rs1 * gp[e] + bp[e];
    }

    const float* cxp = (const float*)&cxv;

    float og[4], cc[4];
    float s2 = 0.f, ss2 = 0.f;
#pragma unroll
    for (int e = 0; e < 4; e++) {
        const float ig = sigm(gate[0][e]);
        const float fg = sigm(gate[1][e]);
        const float cg = ftanh(gate[2][e]);
        og[e] = sigm(gate[3][e]);
        cc[e] = fg * cxp[e] + ig * cg;
        s2 += cc[e];
        ss2 += cc[e] * cc[e];
    }
#pragma unroll
    for (int o = 16; o > 0; o >>= 1) {
        s2  += __shfl_xor_sync(0xffffffffu, s2, o);
        ss2 += __shfl_xor_sync(0xffffffffu, ss2, o);
    }
    if (l == 0) { red2[w] = s2; red2[8 + w] = ss2; }
    __syncthreads();
    float ts2 = 0.f, tss2 = 0.f;
#pragma unroll
    for (int q = 0; q < 8; q++) { ts2 += red2[q]; tss2 += red2[8 + q]; }
    const float mu2 = ts2 * (1.0f / 1024.0f);
    const float var2 = tss2 * (1.0f / 1024.0f) - mu2 * mu2;
    const float rs2 = rsqrtf(var2 + 1e-5f);

    float4 gcv = __ldg((const float4*)gc + t);
    float4 bcv = __ldg((const float4*)bc + t);
    const float* gcp = (const float*)&gcv;
    const float* bcp = (const float*)&bcv;

    float4 hy4, cy4;
    float* hyp = (float*)&hy4;
    float* cyp = (float*)&cy4;
#pragma unroll
    for (int e = 0; e < 4; e++) {
        const float cyv = (cc[e] - mu2) * rs2 * gcp[e] + bcp[e];
        cyp[e] = cyv;
        hyp[e] = og[e] * ftanh(cyv);
    }

    stcs4(out + (size_t)b * H_DIM + t * 4, hy4);
    stcs4(out + (size_t)B_DIM * H_DIM + (size_t)b * H_DIM + t * 4, cy4);
}

// ============================================================================
// Entry point
// ============================================================================
extern "C" void kernel_launch(void* const* d_in, const int* in_sizes, int n_in,
                              void* d_out, int out_size) {
    (void)in_sizes; (void)n_in; (void)out_size;
    const float* inp = (const float*)d_in[0];
    const float* hx  = (const float*)d_in[1];
    const float* cx  = (const float*)d_in[2];
    const float* w   = (const float*)d_in[3];
    const float* gh  = (const float*)d_in[4];
    const float* bh  = (const float*)d_in[5];
    const float* gc  = (const float*)d_in[6];
    const float* bc  = (const float*)d_in[7];
    float* out = (float*)d_out;

    round_all_kernel<<<W_N4 / 256, 256>>>(hx, w);

    cudaFuncSetAttribute(gemm_f16_kernel,
                         cudaFuncAttributeMaxDynamicSharedMemorySize,
                         SMEM_BYTES);
    gemm_f16_kernel<<<dim3(FH_DIM / TN, B_DIM / TM), 128, SMEM_BYTES>>>();

    lstm_ln_kernel<<<B_DIM, 256>>>(inp, cx, gh, bh, gc, bc, out);
}